// round 7
// baseline (speedup 1.0000x reference)
#include <cuda_runtime.h>
#include <cuda_bf16.h>
#include <math.h>
#include <stdint.h>

#define E_ 8
#define D_ 1024
#define H_ 2048
#define T_ 2048

#define BM 128
#define BN 128
#define BK 16
#define NTHR 128    // 4 warps, 64x64 warp tiles

// SMEM stage geometry (floats)
#define A_STRIDE 20            // 16 + 4 pad -> conflict-free A frag loads
#define B_STRIDE 136           // 128 + 8 pad -> conflict-free B frag loads
#define A_FLOATS (BM * A_STRIDE)            // 2560
#define B_FLOATS (BK * B_STRIDE)            // 2176
#define STG_FLOATS (A_FLOATS + B_FLOATS)    // 4736
#define STG_BYTES (STG_FLOATS * 4)          // 18944
#define NSTAGE 4
#define SMEM_BYTES (NSTAGE * STG_BYTES)     // 75776

// ---------------------------------------------------------------------------
// Device scratch (allocation-free per harness rules)
// ---------------------------------------------------------------------------
__device__ float g_h[(size_t)E_ * T_ * H_];     // hidden activations (fp32)
__device__ int   g_cnt[E_];
__device__ int   g_tok[E_ * T_];
__device__ float g_wt[E_ * T_];

// ---------------------------------------------------------------------------
__device__ __forceinline__ uint32_t f2tf32(float v) {
    uint32_t r;
    asm("cvt.rna.tf32.f32 %0, %1;" : "=r"(r) : "f"(v));
    return r;
}

__device__ __forceinline__ void mma_tf32(float* c, const uint32_t* a, const uint32_t* b) {
    asm volatile(
        "mma.sync.aligned.m16n8k8.row.col.f32.tf32.tf32.f32 "
        "{%0,%1,%2,%3}, {%4,%5,%6,%7}, {%8,%9}, {%0,%1,%2,%3};"
        : "+f"(c[0]), "+f"(c[1]), "+f"(c[2]), "+f"(c[3])
        : "r"(a[0]), "r"(a[1]), "r"(a[2]), "r"(a[3]), "r"(b[0]), "r"(b[1]));
}

__device__ __forceinline__ uint32_t smem_u32(const void* p) {
    uint32_t a;
    asm("{ .reg .u64 t; cvta.to.shared.u64 t, %1; cvt.u32.u64 %0, t; }"
        : "=r"(a) : "l"(p));
    return a;
}

#define CP16(dst, src) \
    asm volatile("cp.async.cg.shared.global [%0], [%1], 16;" :: "r"(dst), "l"(src))
#define CP_COMMIT() asm volatile("cp.async.commit_group;")
#define CP_WAIT2()  asm volatile("cp.async.wait_group 2;")

__device__ __forceinline__ float gelu_tanh(float v) {
    float v3 = v * v * v;
    return 0.5f * v * (1.f + tanhf(0.7978845608028654f * (v + 0.044715f * v3)));
}

// ---------------------------------------------------------------------------
// Kernel: zero output + counters
// ---------------------------------------------------------------------------
__global__ void zero_kernel(float* __restrict__ out) {
    size_t i = (size_t)blockIdx.x * blockDim.x + threadIdx.x;
    ((float4*)out)[i] = make_float4(0.f, 0.f, 0.f, 0.f);
    if (blockIdx.x == 0 && threadIdx.x < E_) g_cnt[threadIdx.x] = 0;
}

// ---------------------------------------------------------------------------
// Kernel: gate (verified)
// ---------------------------------------------------------------------------
__global__ __launch_bounds__(256) void gate_kernel(
    const float* __restrict__ x, const float* __restrict__ Wg,
    const float* __restrict__ bg, float* __restrict__ out)
{
    int t = blockIdx.x;
    const float* xr = x + (size_t)t * D_;

    float acc[E_];
#pragma unroll
    for (int e = 0; e < E_; e++) acc[e] = 0.f;

    for (int d = threadIdx.x; d < D_; d += 256) {
        float xv = xr[d];
        const float4* wr = (const float4*)(Wg + (size_t)d * E_);
        float4 w0 = wr[0], w1 = wr[1];
        acc[0] += xv * w0.x; acc[1] += xv * w0.y;
        acc[2] += xv * w0.z; acc[3] += xv * w0.w;
        acc[4] += xv * w1.x; acc[5] += xv * w1.y;
        acc[6] += xv * w1.z; acc[7] += xv * w1.w;
    }
#pragma unroll
    for (int off = 16; off > 0; off >>= 1)
#pragma unroll
        for (int e = 0; e < E_; e++)
            acc[e] += __shfl_down_sync(0xffffffffu, acc[e], off);

    __shared__ float sm[8][E_];
    int warp = threadIdx.x >> 5, lane = threadIdx.x & 31;
    if (lane == 0)
#pragma unroll
        for (int e = 0; e < E_; e++) sm[warp][e] = acc[e];
    __syncthreads();

    if (threadIdx.x == 0) {
        float lg[E_];
#pragma unroll
        for (int e = 0; e < E_; e++) {
            float s = bg[e];
#pragma unroll
            for (int w = 0; w < 8; w++) s += sm[w][e];
            lg[e] = s;
        }
        int e0 = 0;
#pragma unroll
        for (int e = 1; e < E_; e++) if (lg[e] > lg[e0]) e0 = e;
        int e1 = -1;
#pragma unroll
        for (int e = 0; e < E_; e++)
            if (e != e0 && (e1 < 0 || lg[e] > lg[e1])) e1 = e;

        float ex = expf(lg[e1] - lg[e0]);
        float inv = 1.f / (1.f + ex);
        float w0 = inv, w1 = ex * inv;

        out[(size_t)T_ * D_ + 2 * t]     = (float)e0;
        out[(size_t)T_ * D_ + 2 * t + 1] = (float)e1;

        int p0 = atomicAdd(&g_cnt[e0], 1);
        g_tok[e0 * T_ + p0] = t;  g_wt[e0 * T_ + p0] = w0;
        int p1 = atomicAdd(&g_cnt[e1], 1);
        g_tok[e1 * T_ + p1] = t;  g_wt[e1 * T_ + p1] = w1;
    }
}

// ===========================================================================
// 4-stage cp.async tf32 GEMM mainloop, 4 warps @ 64x64 warp tiles.
//   A smem [m][k] stride 20, B smem [k][n] stride 136 (raw fp32).
//   cvt.rna.tf32 applied on fragments in registers (numerics == prepass).
//   Staging (128 thr, 4 segments each):
//     A seg: row = seg>>2, ksub = (seg&3)*4
//     B seg: k = seg>>5,  nsub = (seg&31)*4
// ===========================================================================
template <int NCH>
__device__ __forceinline__ void gemm_pipe(
    float* sm, uint32_t smb,
    const float* const* asrc,    // [4] per-seg A source ptrs (chunk 0)
    const float* const* bsrc,    // [4] per-seg B source ptrs (chunk 0)
    int bstride, float acc[4][8][4])
{
    const int tid = threadIdx.x;
    const int lane = tid & 31, wid = tid >> 5;
    const int wm = wid & 1, wn = wid >> 1;       // 2x2 warp grid, 64x64 each
    const int t4 = lane & 3, g8 = lane >> 2;

    uint32_t dA[4], dB[4];
#pragma unroll
    for (int j = 0; j < 4; j++) {
        int seg = tid + NTHR * j;
        dA[j] = (uint32_t)(((seg >> 2) * A_STRIDE + (seg & 3) * 4) * 4);
        dB[j] = (uint32_t)(A_FLOATS * 4 + ((seg >> 5) * B_STRIDE + (seg & 31) * 4) * 4);
    }

#pragma unroll
    for (int i = 0; i < 4; i++)
#pragma unroll
        for (int j = 0; j < 8; j++)
#pragma unroll
            for (int q = 0; q < 4; q++) acc[i][j][q] = 0.f;

    // prologue: stages 0..2 <- chunks 0..2
#pragma unroll
    for (int s = 0; s < NSTAGE - 1; s++) {
        uint32_t base = smb + s * STG_BYTES;
        size_t bo = (size_t)s * BK * bstride;
#pragma unroll
        for (int j = 0; j < 4; j++) {
            CP16(base + dA[j], asrc[j] + s * BK);
            CP16(base + dB[j], bsrc[j] + bo);
        }
        CP_COMMIT();
    }

    for (int ch = 0; ch < NCH; ++ch) {
        CP_WAIT2();
        __syncthreads();

        const int s = ch & (NSTAGE - 1);
        const float* As = sm + s * STG_FLOATS;                 // [m][k] str 20
        const float* Bsm = sm + s * STG_FLOATS + A_FLOATS;     // [k][n] str 136

#pragma unroll
        for (int kh = 0; kh < 2; ++kh) {
            const int k0 = kh * 8;
            uint32_t af[4][4], bf[8][2];
#pragma unroll
            for (int mi = 0; mi < 4; mi++) {
                int rm = wm * 64 + mi * 16;
                const float* r0 = As + (rm + g8) * A_STRIDE + k0 + t4;
                const float* r1 = As + (rm + g8 + 8) * A_STRIDE + k0 + t4;
                af[mi][0] = f2tf32(r0[0]);
                af[mi][1] = f2tf32(r1[0]);
                af[mi][2] = f2tf32(r0[4]);
                af[mi][3] = f2tf32(r1[4]);
            }
#pragma unroll
            for (int ni = 0; ni < 8; ni++) {
                int cb = wn * 64 + ni * 8 + g8;
                bf[ni][0] = f2tf32(Bsm[(k0 + t4) * B_STRIDE + cb]);
                bf[ni][1] = f2tf32(Bsm[(k0 + t4 + 4) * B_STRIDE + cb]);
            }
#pragma unroll
            for (int mi = 0; mi < 4; mi++)
#pragma unroll
                for (int ni = 0; ni < 8; ni++)
                    mma_tf32(acc[mi][ni], af[mi], bf[ni]);
        }

        int nch = ch + NSTAGE - 1;
        if (nch < NCH) {
            uint32_t base = smb + (nch & (NSTAGE - 1)) * STG_BYTES;
            size_t bo = (size_t)nch * BK * bstride;
#pragma unroll
            for (int j = 0; j < 4; j++) {
                CP16(base + dA[j], asrc[j] + nch * BK);
                CP16(base + dB[j], bsrc[j] + bo);
            }
        }
        CP_COMMIT();   // commit every iter to keep group accounting in sync
    }
}

// ---------------------------------------------------------------------------
// GEMM1: h[slot] = gelu(X[tok] @ W1[e] + b1[e])
// ---------------------------------------------------------------------------
__global__ __launch_bounds__(NTHR) void gemm1_mma(
    const float* __restrict__ X, const float* __restrict__ W1,
    const float* __restrict__ b1)
{
    int e = blockIdx.z;
    int ne = g_cnt[e];
    int row0 = blockIdx.x * BM;
    if (row0 >= ne) return;
    int n0 = blockIdx.y * BN;

    extern __shared__ float sm[];
    uint32_t smb = smem_u32(sm);
    __shared__ int s_tok[BM];

    int tid = threadIdx.x;
#pragma unroll
    for (int j = 0; j < BM / NTHR; j++) {
        int rr = tid + NTHR * j;
        int r = row0 + rr;
        s_tok[rr] = (r < ne) ? g_tok[e * T_ + r] : 0;
    }
    __syncthreads();

    const float* asrc[4];
    const float* bsrc[4];
    const float* wbase = W1 + (size_t)e * D_ * H_ + n0;
#pragma unroll
    for (int j = 0; j < 4; j++) {
        int seg = tid + NTHR * j;
        asrc[j] = X + (size_t)s_tok[seg >> 2] * D_ + (seg & 3) * 4;
        bsrc[j] = wbase + (size_t)(seg >> 5) * H_ + (seg & 31) * 4;
    }

    float acc[4][8][4];
    gemm_pipe<D_ / BK>(sm, smb, asrc, bsrc, H_, acc);

    const int lane = tid & 31, wid = tid >> 5;
    const int wm = wid & 1, wn = wid >> 1;
    const int t4 = lane & 3, g8 = lane >> 2;
    const float* bb = b1 + (size_t)e * H_ + n0;
#pragma unroll
    for (int mi = 0; mi < 4; mi++) {
        int rl0 = wm * 64 + mi * 16 + g8;
#pragma unroll
        for (int half = 0; half < 2; half++) {
            int r = row0 + rl0 + half * 8;
            if (r >= ne) continue;
            float* orow = g_h + ((size_t)(e * T_ + r)) * H_ + n0;
#pragma unroll
            for (int ni = 0; ni < 8; ni++) {
                int cn = wn * 64 + ni * 8 + t4 * 2;
                float v0 = acc[mi][ni][half * 2]     + bb[cn];
                float v1 = acc[mi][ni][half * 2 + 1] + bb[cn + 1];
                float2 o = make_float2(gelu_tanh(v0), gelu_tanh(v1));
                *(float2*)(orow + cn) = o;
            }
        }
    }
}

// ---------------------------------------------------------------------------
// GEMM2: out[tok] += w * (h[slot] @ W2[e] + b2[e])
// ---------------------------------------------------------------------------
__global__ __launch_bounds__(NTHR) void gemm2_mma(
    const float* __restrict__ W2, const float* __restrict__ b2,
    float* __restrict__ out)
{
    int e = blockIdx.z;
    int ne = g_cnt[e];
    int row0 = blockIdx.x * BM;
    if (row0 >= ne) return;
    int n0 = blockIdx.y * BN;

    extern __shared__ float sm[];
    uint32_t smb = smem_u32(sm);

    int tid = threadIdx.x;
    const float* asrc[4];
    const float* bsrc[4];
    const float* wbase = W2 + (size_t)e * H_ * D_ + n0;
#pragma unroll
    for (int j = 0; j < 4; j++) {
        int seg = tid + NTHR * j;
        // rows >= ne read stale-but-finite scratch; masked in epilogue
        asrc[j] = g_h + ((size_t)(e * T_ + row0 + (seg >> 2))) * H_ + (seg & 3) * 4;
        bsrc[j] = wbase + (size_t)(seg >> 5) * D_ + (seg & 31) * 4;
    }

    float acc[4][8][4];
    gemm_pipe<H_ / BK>(sm, smb, asrc, bsrc, D_, acc);

    const int lane = tid & 31, wid = tid >> 5;
    const int wm = wid & 1, wn = wid >> 1;
    const int t4 = lane & 3, g8 = lane >> 2;
    const float* bb = b2 + (size_t)e * D_ + n0;
#pragma unroll
    for (int mi = 0; mi < 4; mi++) {
        int rl0 = wm * 64 + mi * 16 + g8;
#pragma unroll
        for (int half = 0; half < 2; half++) {
            int r = row0 + rl0 + half * 8;
            if (r >= ne) continue;
            int tok = g_tok[e * T_ + r];
            float wgt = g_wt[e * T_ + r];
            float* orow = out + (size_t)tok * D_ + n0;
#pragma unroll
            for (int ni = 0; ni < 8; ni++) {
                int cn = wn * 64 + ni * 8 + t4 * 2;
                atomicAdd(orow + cn,     wgt * (acc[mi][ni][half * 2]     + bb[cn]));
                atomicAdd(orow + cn + 1, wgt * (acc[mi][ni][half * 2 + 1] + bb[cn + 1]));
            }
        }
    }
}

// ---------------------------------------------------------------------------
extern "C" void kernel_launch(void* const* d_in, const int* in_sizes, int n_in,
                              void* d_out, int out_size)
{
    const float* x  = (const float*)d_in[0];
    const float* Wg = (const float*)d_in[1];
    const float* bg = (const float*)d_in[2];
    const float* W1 = (const float*)d_in[3];
    const float* b1 = (const float*)d_in[4];
    const float* W2 = (const float*)d_in[5];
    const float* b2 = (const float*)d_in[6];
    float* out = (float*)d_out;

    static int attr_set = 0;
    if (!attr_set) {
        cudaFuncSetAttribute(gemm1_mma, cudaFuncAttributeMaxDynamicSharedMemorySize, SMEM_BYTES);
        cudaFuncSetAttribute(gemm2_mma, cudaFuncAttributeMaxDynamicSharedMemorySize, SMEM_BYTES);
        attr_set = 1;
    }

    zero_kernel<<<(T_ * D_) / (256 * 4), 256>>>(out);
    gate_kernel<<<T_, 256>>>(x, Wg, bg, out);
    gemm1_mma<<<dim3(T_ / BM, H_ / BN, E_), NTHR, SMEM_BYTES>>>(x, W1, b1);
    gemm2_mma<<<dim3(T_ / BM, D_ / BN, E_), NTHR, SMEM_BYTES>>>(W2, b2, out);
}

// round 8
// speedup vs baseline: 1.2557x; 1.2557x over previous
#include <cuda_runtime.h>
#include <cuda_bf16.h>
#include <math.h>
#include <stdint.h>

#define E_ 8
#define D_ 1024
#define H_ 2048
#define T_ 2048

#define BM 128
#define BN 256
#define BK 16
#define NTHR 256    // 8 warps, 2x4 grid of 64x64 warp tiles

// SMEM stage geometry (floats)
#define A_STRIDE 20            // 16 + 4 pad -> conflict-free A frag loads
#define B_STRIDE 264           // 256 + 8 pad -> conflict-free B frag loads
#define A_FLOATS (BM * A_STRIDE)            // 2560
#define B_FLOATS (BK * B_STRIDE)            // 4224
#define STG_FLOATS (A_FLOATS + B_FLOATS)    // 6784
#define STG_BYTES (STG_FLOATS * 4)          // 27136
#define NSTAGE 4
#define SMEM_BYTES (NSTAGE * STG_BYTES)     // 108544

// ---------------------------------------------------------------------------
// Device scratch (allocation-free per harness rules)
// ---------------------------------------------------------------------------
__device__ float g_h[(size_t)E_ * T_ * H_];     // hidden acts (tf32-rounded fp32)
__device__ float g_Xr[(size_t)T_ * D_];         // X  tf32-rounded
__device__ float g_W1r[(size_t)E_ * D_ * H_];   // W1 tf32-rounded
__device__ float g_W2r[(size_t)E_ * H_ * D_];   // W2 tf32-rounded
__device__ int   g_cnt[E_];
__device__ int   g_tok[E_ * T_];
__device__ float g_wt[E_ * T_];

// ---------------------------------------------------------------------------
__device__ __forceinline__ uint32_t f2tf32(float v) {
    uint32_t r;
    asm("cvt.rna.tf32.f32 %0, %1;" : "=r"(r) : "f"(v));
    return r;
}

__device__ __forceinline__ void mma_tf32(float* c, const uint32_t* a, const uint32_t* b) {
    asm volatile(
        "mma.sync.aligned.m16n8k8.row.col.f32.tf32.tf32.f32 "
        "{%0,%1,%2,%3}, {%4,%5,%6,%7}, {%8,%9}, {%0,%1,%2,%3};"
        : "+f"(c[0]), "+f"(c[1]), "+f"(c[2]), "+f"(c[3])
        : "r"(a[0]), "r"(a[1]), "r"(a[2]), "r"(a[3]), "r"(b[0]), "r"(b[1]));
}

__device__ __forceinline__ uint32_t smem_u32(const void* p) {
    uint32_t a;
    asm("{ .reg .u64 t; cvta.to.shared.u64 t, %1; cvt.u32.u64 %0, t; }"
        : "=r"(a) : "l"(p));
    return a;
}

#define CP16(dst, src) \
    asm volatile("cp.async.cg.shared.global [%0], [%1], 16;" :: "r"(dst), "l"(src))
#define CP_COMMIT() asm volatile("cp.async.commit_group;")
#define CP_WAIT2()  asm volatile("cp.async.wait_group 2;")

__device__ __forceinline__ float gelu_tanh(float v) {
    float v3 = v * v * v;
    return 0.5f * v * (1.f + tanhf(0.7978845608028654f * (v + 0.044715f * v3)));
}

// ---------------------------------------------------------------------------
// Kernel: zero output + counters
// ---------------------------------------------------------------------------
__global__ void zero_kernel(float* __restrict__ out) {
    size_t i = (size_t)blockIdx.x * blockDim.x + threadIdx.x;
    ((float4*)out)[i] = make_float4(0.f, 0.f, 0.f, 0.f);
    if (blockIdx.x == 0 && threadIdx.x < E_) g_cnt[threadIdx.x] = 0;
}

// ---------------------------------------------------------------------------
// Kernel: tf32 round pre-pass
// ---------------------------------------------------------------------------
__global__ void rnd_kernel(const float* __restrict__ s, float* __restrict__ d) {
    size_t i = ((size_t)blockIdx.x * 256 + threadIdx.x) * 4;
    float4 v = *(const float4*)(s + i);
    uint4 o;
    o.x = f2tf32(v.x); o.y = f2tf32(v.y); o.z = f2tf32(v.z); o.w = f2tf32(v.w);
    *(uint4*)(d + i) = o;
}

// ---------------------------------------------------------------------------
// Kernel: gate (verified)
// ---------------------------------------------------------------------------
__global__ __launch_bounds__(256) void gate_kernel(
    const float* __restrict__ x, const float* __restrict__ Wg,
    const float* __restrict__ bg, float* __restrict__ out)
{
    int t = blockIdx.x;
    const float* xr = x + (size_t)t * D_;

    float acc[E_];
#pragma unroll
    for (int e = 0; e < E_; e++) acc[e] = 0.f;

    for (int d = threadIdx.x; d < D_; d += 256) {
        float xv = xr[d];
        const float4* wr = (const float4*)(Wg + (size_t)d * E_);
        float4 w0 = wr[0], w1 = wr[1];
        acc[0] += xv * w0.x; acc[1] += xv * w0.y;
        acc[2] += xv * w0.z; acc[3] += xv * w0.w;
        acc[4] += xv * w1.x; acc[5] += xv * w1.y;
        acc[6] += xv * w1.z; acc[7] += xv * w1.w;
    }
#pragma unroll
    for (int off = 16; off > 0; off >>= 1)
#pragma unroll
        for (int e = 0; e < E_; e++)
            acc[e] += __shfl_down_sync(0xffffffffu, acc[e], off);

    __shared__ float sm[8][E_];
    int warp = threadIdx.x >> 5, lane = threadIdx.x & 31;
    if (lane == 0)
#pragma unroll
        for (int e = 0; e < E_; e++) sm[warp][e] = acc[e];
    __syncthreads();

    if (threadIdx.x == 0) {
        float lg[E_];
#pragma unroll
        for (int e = 0; e < E_; e++) {
            float s = bg[e];
#pragma unroll
            for (int w = 0; w < 8; w++) s += sm[w][e];
            lg[e] = s;
        }
        int e0 = 0;
#pragma unroll
        for (int e = 1; e < E_; e++) if (lg[e] > lg[e0]) e0 = e;
        int e1 = -1;
#pragma unroll
        for (int e = 0; e < E_; e++)
            if (e != e0 && (e1 < 0 || lg[e] > lg[e1])) e1 = e;

        float ex = expf(lg[e1] - lg[e0]);
        float inv = 1.f / (1.f + ex);
        float w0 = inv, w1 = ex * inv;

        out[(size_t)T_ * D_ + 2 * t]     = (float)e0;
        out[(size_t)T_ * D_ + 2 * t + 1] = (float)e1;

        int p0 = atomicAdd(&g_cnt[e0], 1);
        g_tok[e0 * T_ + p0] = t;  g_wt[e0 * T_ + p0] = w0;
        int p1 = atomicAdd(&g_cnt[e1], 1);
        g_tok[e1 * T_ + p1] = t;  g_wt[e1 * T_ + p1] = w1;
    }
}

// ===========================================================================
// 4-stage cp.async tf32 GEMM mainloop. 128x256 block tile, BK=16, 256 thr,
// 8 warps in 2x4 grid of 64x64 warp tiles. Operands pre-rounded (raw bits).
//   A smem [m][k] stride 20, B smem [k][n] stride 264.
//   Staging per chunk (256 thr):
//     A: 2 segs: seg=tid+256j -> row=seg>>2, ksub=(seg&3)*4
//     B: 4 segs: seg=tid+256j -> k=seg>>6,  nsub=(seg&63)*4
// ===========================================================================
template <int NCH>
__device__ __forceinline__ void gemm_pipe(
    float* sm, uint32_t smb,
    const float* const* asrc,    // [2] per-seg A source ptrs (chunk 0)
    const float* const* bsrc,    // [4] per-seg B source ptrs (chunk 0)
    int bstride, float acc[4][8][4])
{
    const int tid = threadIdx.x;
    const int lane = tid & 31, wid = tid >> 5;
    const int wm = wid & 1, wn = wid >> 1;
    const int t4 = lane & 3, g8 = lane >> 2;

    uint32_t dA[2], dB[4];
#pragma unroll
    for (int j = 0; j < 2; j++) {
        int seg = tid + NTHR * j;
        dA[j] = (uint32_t)(((seg >> 2) * A_STRIDE + (seg & 3) * 4) * 4);
    }
#pragma unroll
    for (int j = 0; j < 4; j++) {
        int seg = tid + NTHR * j;
        dB[j] = (uint32_t)(A_FLOATS * 4 + ((seg >> 6) * B_STRIDE + (seg & 63) * 4) * 4);
    }

#pragma unroll
    for (int i = 0; i < 4; i++)
#pragma unroll
        for (int j = 0; j < 8; j++)
#pragma unroll
            for (int q = 0; q < 4; q++) acc[i][j][q] = 0.f;

    // prologue: stages 0..2 <- chunks 0..2
#pragma unroll
    for (int s = 0; s < NSTAGE - 1; s++) {
        uint32_t base = smb + s * STG_BYTES;
        size_t bo = (size_t)s * BK * bstride;
#pragma unroll
        for (int j = 0; j < 2; j++) CP16(base + dA[j], asrc[j] + s * BK);
#pragma unroll
        for (int j = 0; j < 4; j++) CP16(base + dB[j], bsrc[j] + bo);
        CP_COMMIT();
    }

    for (int ch = 0; ch < NCH; ++ch) {
        CP_WAIT2();
        __syncthreads();

        const int s = ch & (NSTAGE - 1);
        const float* As = sm + s * STG_FLOATS;                 // [m][k] str 20
        const float* Bsm = sm + s * STG_FLOATS + A_FLOATS;     // [k][n] str 264

#pragma unroll
        for (int kh = 0; kh < 2; ++kh) {
            const int k0 = kh * 8;
            uint32_t af[4][4], bf[8][2];
#pragma unroll
            for (int mi = 0; mi < 4; mi++) {
                int rm = wm * 64 + mi * 16;
                const float* r0 = As + (rm + g8) * A_STRIDE + k0 + t4;
                const float* r1 = As + (rm + g8 + 8) * A_STRIDE + k0 + t4;
                af[mi][0] = __float_as_uint(r0[0]);
                af[mi][1] = __float_as_uint(r1[0]);
                af[mi][2] = __float_as_uint(r0[4]);
                af[mi][3] = __float_as_uint(r1[4]);
            }
#pragma unroll
            for (int ni = 0; ni < 8; ni++) {
                int cb = wn * 64 + ni * 8 + g8;
                bf[ni][0] = __float_as_uint(Bsm[(k0 + t4) * B_STRIDE + cb]);
                bf[ni][1] = __float_as_uint(Bsm[(k0 + t4 + 4) * B_STRIDE + cb]);
            }
#pragma unroll
            for (int mi = 0; mi < 4; mi++)
#pragma unroll
                for (int ni = 0; ni < 8; ni++)
                    mma_tf32(acc[mi][ni], af[mi], bf[ni]);
        }

        int nch = ch + NSTAGE - 1;
        if (nch < NCH) {
            uint32_t base = smb + (nch & (NSTAGE - 1)) * STG_BYTES;
            size_t bo = (size_t)nch * BK * bstride;
#pragma unroll
            for (int j = 0; j < 2; j++) CP16(base + dA[j], asrc[j] + nch * BK);
#pragma unroll
            for (int j = 0; j < 4; j++) CP16(base + dB[j], bsrc[j] + bo);
        }
        CP_COMMIT();   // commit every iter to keep group accounting in sync
    }
}

// ---------------------------------------------------------------------------
// GEMM1: h[slot] = tf32round(gelu(Xr[tok] @ W1r[e] + b1[e]))
// ---------------------------------------------------------------------------
__global__ __launch_bounds__(NTHR, 1) void gemm1_mma(const float* __restrict__ b1)
{
    int e = blockIdx.z;
    int ne = g_cnt[e];
    int row0 = blockIdx.x * BM;
    if (row0 >= ne) return;
    int n0 = blockIdx.y * BN;

    extern __shared__ float sm[];
    uint32_t smb = smem_u32(sm);
    __shared__ int s_tok[BM];

    int tid = threadIdx.x;
    if (tid < BM) {
        int r = row0 + tid;
        s_tok[tid] = (r < ne) ? g_tok[e * T_ + r] : 0;
    }
    __syncthreads();

    const float* asrc[2];
    const float* bsrc[4];
    const float* wbase = g_W1r + (size_t)e * D_ * H_ + n0;
#pragma unroll
    for (int j = 0; j < 2; j++) {
        int seg = tid + NTHR * j;
        asrc[j] = g_Xr + (size_t)s_tok[seg >> 2] * D_ + (seg & 3) * 4;
    }
#pragma unroll
    for (int j = 0; j < 4; j++) {
        int seg = tid + NTHR * j;
        bsrc[j] = wbase + (size_t)(seg >> 6) * H_ + (seg & 63) * 4;
    }

    float acc[4][8][4];
    gemm_pipe<D_ / BK>(sm, smb, asrc, bsrc, H_, acc);

    const int lane = tid & 31, wid = tid >> 5;
    const int wm = wid & 1, wn = wid >> 1;
    const int t4 = lane & 3, g8 = lane >> 2;
    const float* bb = b1 + (size_t)e * H_ + n0;
#pragma unroll
    for (int mi = 0; mi < 4; mi++) {
        int rl0 = wm * 64 + mi * 16 + g8;
#pragma unroll
        for (int half = 0; half < 2; half++) {
            int r = row0 + rl0 + half * 8;
            if (r >= ne) continue;
            float* orow = g_h + ((size_t)(e * T_ + r)) * H_ + n0;
#pragma unroll
            for (int ni = 0; ni < 8; ni++) {
                int cn = wn * 64 + ni * 8 + t4 * 2;
                float v0 = acc[mi][ni][half * 2]     + bb[cn];
                float v1 = acc[mi][ni][half * 2 + 1] + bb[cn + 1];
                float2 o;
                o.x = __uint_as_float(f2tf32(gelu_tanh(v0)));
                o.y = __uint_as_float(f2tf32(gelu_tanh(v1)));
                *(float2*)(orow + cn) = o;
            }
        }
    }
}

// ---------------------------------------------------------------------------
// GEMM2: out[tok] += w * (h[slot] @ W2r[e] + b2[e])
// ---------------------------------------------------------------------------
__global__ __launch_bounds__(NTHR, 1) void gemm2_mma(const float* __restrict__ b2,
                                                     float* __restrict__ out)
{
    int e = blockIdx.z;
    int ne = g_cnt[e];
    int row0 = blockIdx.x * BM;
    if (row0 >= ne) return;
    int n0 = blockIdx.y * BN;

    extern __shared__ float sm[];
    uint32_t smb = smem_u32(sm);

    int tid = threadIdx.x;
    const float* asrc[2];
    const float* bsrc[4];
    const float* wbase = g_W2r + (size_t)e * H_ * D_ + n0;
#pragma unroll
    for (int j = 0; j < 2; j++) {
        int seg = tid + NTHR * j;
        // rows >= ne read stale-but-finite scratch; masked in epilogue
        asrc[j] = g_h + ((size_t)(e * T_ + row0 + (seg >> 2))) * H_ + (seg & 3) * 4;
    }
#pragma unroll
    for (int j = 0; j < 4; j++) {
        int seg = tid + NTHR * j;
        bsrc[j] = wbase + (size_t)(seg >> 6) * D_ + (seg & 63) * 4;
    }

    float acc[4][8][4];
    gemm_pipe<H_ / BK>(sm, smb, asrc, bsrc, D_, acc);

    const int lane = tid & 31, wid = tid >> 5;
    const int wm = wid & 1, wn = wid >> 1;
    const int t4 = lane & 3, g8 = lane >> 2;
    const float* bb = b2 + (size_t)e * D_ + n0;
#pragma unroll
    for (int mi = 0; mi < 4; mi++) {
        int rl0 = wm * 64 + mi * 16 + g8;
#pragma unroll
        for (int half = 0; half < 2; half++) {
            int r = row0 + rl0 + half * 8;
            if (r >= ne) continue;
            int tok = g_tok[e * T_ + r];
            float wgt = g_wt[e * T_ + r];
            float* orow = out + (size_t)tok * D_ + n0;
#pragma unroll
            for (int ni = 0; ni < 8; ni++) {
                int cn = wn * 64 + ni * 8 + t4 * 2;
                atomicAdd(orow + cn,     wgt * (acc[mi][ni][half * 2]     + bb[cn]));
                atomicAdd(orow + cn + 1, wgt * (acc[mi][ni][half * 2 + 1] + bb[cn + 1]));
            }
        }
    }
}

// ---------------------------------------------------------------------------
extern "C" void kernel_launch(void* const* d_in, const int* in_sizes, int n_in,
                              void* d_out, int out_size)
{
    const float* x  = (const float*)d_in[0];
    const float* Wg = (const float*)d_in[1];
    const float* bg = (const float*)d_in[2];
    const float* W1 = (const float*)d_in[3];
    const float* b1 = (const float*)d_in[4];
    const float* W2 = (const float*)d_in[5];
    const float* b2 = (const float*)d_in[6];
    float* out = (float*)d_out;

    static int attr_set = 0;
    if (!attr_set) {
        cudaFuncSetAttribute(gemm1_mma, cudaFuncAttributeMaxDynamicSharedMemorySize, SMEM_BYTES);
        cudaFuncSetAttribute(gemm2_mma, cudaFuncAttributeMaxDynamicSharedMemorySize, SMEM_BYTES);
        attr_set = 1;
    }

    float* xr;  cudaGetSymbolAddress((void**)&xr,  g_Xr);
    float* w1r; cudaGetSymbolAddress((void**)&w1r, g_W1r);
    float* w2r; cudaGetSymbolAddress((void**)&w2r, g_W2r);

    zero_kernel<<<(T_ * D_) / (256 * 4), 256>>>(out);
    gate_kernel<<<T_, 256>>>(x, Wg, bg, out);
    rnd_kernel<<<(T_ * D_) / 1024, 256>>>(x, xr);
    rnd_kernel<<<(E_ * D_ * H_) / 1024, 256>>>(W1, w1r);
    rnd_kernel<<<(E_ * H_ * D_) / 1024, 256>>>(W2, w2r);
    gemm1_mma<<<dim3(T_ / BM, H_ / BN, E_), NTHR, SMEM_BYTES>>>(b1);
    gemm2_mma<<<dim3(T_ / BM, D_ / BN, E_), NTHR, SMEM_BYTES>>>(b2, out);
}